// round 16
// baseline (speedup 1.0000x reference)
#include <cuda_runtime.h>
#include <cuda_fp16.h>
#include <cstdint>
#include <math.h>
#include <string.h>

// Problem shape (fixed)
#define BB 4
#define SS 2048
#define DD 1024
#define HH 16
#define DH 64
#define MROWS (BB*SS)   // 8192

// ---------------------------------------------------------------------------
// Scratch (__device__ globals). Single-fp16 everywhere.
// q/k/v layout: [B*H][S][64]
// ---------------------------------------------------------------------------
__device__ __half g_q[(size_t)BB*HH*SS*DH];
__device__ __half g_k[(size_t)BB*HH*SS*DH];
__device__ __half g_v[(size_t)BB*HH*SS*DH];

__device__ __half g_x16[(size_t)MROWS*DD];
__device__ __half g_at16[(size_t)MROWS*DD];
// transposed weights: [4][N][K], Wt[n][k] = W[k][n]; 0..3 = q,k,v,o
__device__ __half g_wt[(size_t)4*DD*DD];

// ---------------------------------------------------------------------------
// Helpers (base-sm_103-safe)
// ---------------------------------------------------------------------------
__device__ __forceinline__ uint32_t smem_u32(const void* p) {
    uint32_t a;
    asm("{ .reg .u64 t; cvta.to.shared.u64 t, %1; cvt.u32.u64 %0, t; }"
        : "=r"(a) : "l"(p));
    return a;
}
#define CP_ASYNC16(dst_u32, src_ptr) \
    asm volatile("cp.async.cg.shared.global [%0], [%1], 16;" \
                 :: "r"(dst_u32), "l"(src_ptr))
#define CP_COMMIT() asm volatile("cp.async.commit_group;")
#define CP_WAIT1()  asm volatile("cp.async.wait_group 1;")

#define LDSM_X4(r0, r1, r2, r3, addr) \
    asm volatile("ldmatrix.sync.aligned.m8n8.x4.shared.b16 {%0,%1,%2,%3}, [%4];" \
                 : "=r"(r0), "=r"(r1), "=r"(r2), "=r"(r3) : "r"(addr))
#define LDSM_X4_T(r0, r1, r2, r3, addr) \
    asm volatile("ldmatrix.sync.aligned.m8n8.x4.trans.shared.b16 {%0,%1,%2,%3}, [%4];" \
                 : "=r"(r0), "=r"(r1), "=r"(r2), "=r"(r3) : "r"(addr))

#define MMA16816(d, a0, a1, a2, a3, b0, b1) \
    asm volatile("mma.sync.aligned.m16n8k16.row.col.f32.f16.f16.f32 " \
                 "{%0,%1,%2,%3}, {%4,%5,%6,%7}, {%8,%9}, {%0,%1,%2,%3};" \
                 : "+f"((d)[0]), "+f"((d)[1]), "+f"((d)[2]), "+f"((d)[3]) \
                 : "r"(a0), "r"(a1), "r"(a2), "r"(a3), "r"(b0), "r"(b1))

// packed f16x2 convert: result = {lo = cvt(a), hi = cvt(b)}  (RN rounding)
__device__ __forceinline__ uint32_t cvt2_f16(float a, float b) {
    uint32_t r;
    asm("cvt.rn.f16x2.f32 %0, %1, %2;" : "=r"(r) : "f"(b), "f"(a));
    return r;
}

// XOR swizzle for exact 128B rows: addr = row*128 + ((chunk ^ (row&7))*16)
__device__ __forceinline__ uint32_t asw(int row, int chunk) {
    return (uint32_t)(row * 128 + ((chunk ^ (row & 7)) << 4));
}

// q scale: (1/sqrt(64)) * log2(e), so softmax runs in exp2 domain
#define QSCALE 0.1803368801111204f

// ---------------------------------------------------------------------------
// Fused prep kernel (unchanged)
// ---------------------------------------------------------------------------
#define NSPLIT ((MROWS * DD) / (256 * 4))   // 8192

__global__ void __launch_bounds__(256)
prep_kernel(const float* __restrict__ x,
            const float* __restrict__ Wq, const float* __restrict__ Wk,
            const float* __restrict__ Wv, const float* __restrict__ Wo,
            __half* __restrict__ x16)
{
    int bid = blockIdx.x;
    if (bid < NSPLIT) {
        size_t i = ((size_t)bid * 256 + threadIdx.x) * 4;
        float4 v = *(const float4*)(x + i);
        *(uint32_t*)(x16 + i)     = cvt2_f16(v.x, v.y);
        *(uint32_t*)(x16 + i + 2) = cvt2_f16(v.z, v.w);
    } else {
        __shared__ float t[32][33];
        int tb = bid - NSPLIT;
        int z  = tb >> 10;
        int rem = tb & 1023;
        int k0 = (rem >> 5) * 32;
        int n0 = (rem & 31) * 32;
        const float* W = (z == 0) ? Wq : (z == 1) ? Wk : (z == 2) ? Wv : Wo;
        __half* Th = g_wt + (size_t)z * DD * DD;
        int tx = threadIdx.x & 31, ty = threadIdx.x >> 5;
        #pragma unroll
        for (int i = ty; i < 32; i += 8)
            t[i][tx] = W[(size_t)(k0 + i) * DD + n0 + tx];
        __syncthreads();
        #pragma unroll
        for (int i = ty; i < 32; i += 8) {
            size_t o = (size_t)(n0 + i) * DD + k0 + tx;
            Th[o] = __float2half(t[tx][i]);
        }
    }
}

// ---------------------------------------------------------------------------
// fp16 GEMM on mma.sync (unchanged from R15: KC=64, single-barrier 3-buffer).
// ---------------------------------------------------------------------------
#define KC 64
#define NCHUNK (DD / KC)              // 16
#define GTILE_BY (128 * 128)          // 16384
#define GSTAGE_BY (2 * GTILE_BY)      // 32768
#define GNSTAGE 3
#define SMEM_MMA (GNSTAGE * GSTAGE_BY)  // 98304
#define GT 128

template<int MODE>
__device__ __forceinline__ void mma_gemm_body(const __half* __restrict__ A,
                                              const __half* __restrict__ B,
                                              const float* __restrict__ bias,
                                              float* __restrict__ C,
                                              __half* __restrict__ Ho,
                                              float scale)
{
    extern __shared__ char dynsmem[];
    const uint32_t base_u = smem_u32(dynsmem);

    const int tid  = threadIdx.x;
    const int wid  = tid >> 5, lane = tid & 31;
    const int wm   = wid & 1;
    const int wn   = wid >> 1;
    const int m0   = blockIdx.y * 128;
    const int n0   = blockIdx.x * 128;

    const __half* srcs[2] = { A, B };
    const int rowbase[2] = { m0, n0 };

    auto issue_stage = [&](int c, int st) {
        #pragma unroll
        for (int tile = 0; tile < 2; ++tile) {
            const __half* src = srcs[tile] + (size_t)rowbase[tile] * DD + c * KC;
            uint32_t dst = base_u + st * GSTAGE_BY + tile * GTILE_BY;
            #pragma unroll
            for (int it = 0; it < 8; ++it) {
                int idx = tid + it * GT;
                int row = idx >> 3;
                int seg = idx & 7;
                CP_ASYNC16(dst + asw(row, seg), src + (size_t)row * DD + seg * 8);
            }
        }
    };

    float acc[4][8][4];
    #pragma unroll
    for (int i = 0; i < 4; ++i)
        #pragma unroll
        for (int j = 0; j < 8; ++j)
            #pragma unroll
            for (int q = 0; q < 4; ++q) acc[i][j][q] = 0.f;

    const int arow_l = (lane & 15);
    const int achk_l = (lane >> 4) & 1;
    const int brow_l = (lane & 7) + ((lane >> 4) & 1) * 8;
    const int bchk_l = (lane >> 3) & 1;

    issue_stage(0, 0); CP_COMMIT();
    issue_stage(1, 1); CP_COMMIT();

    for (int c = 0; c < NCHUNK; ++c) {
        const int st = c % GNSTAGE;
        CP_WAIT1();
        __syncthreads();
        if (c + 2 < NCHUNK) issue_stage(c + 2, (c + 2) % GNSTAGE);
        CP_COMMIT();

        const uint32_t sA = base_u + st * GSTAGE_BY;
        const uint32_t sB = sA + GTILE_BY;

        #pragma unroll
        for (int ks = 0; ks < 4; ++ks) {
            uint32_t ah[4][4];
            #pragma unroll
            for (int mf = 0; mf < 4; ++mf) {
                int ar = wm * 64 + mf * 16 + arow_l;
                LDSM_X4(ah[mf][0], ah[mf][1], ah[mf][2], ah[mf][3],
                        sA + asw(ar, 2 * ks + achk_l));
            }
            #pragma unroll
            for (int ng = 0; ng < 4; ++ng) {
                uint32_t bh[4];
                int br = wn * 64 + ng * 16 + brow_l;
                LDSM_X4(bh[0], bh[1], bh[2], bh[3], sB + asw(br, 2 * ks + bchk_l));
                #pragma unroll
                for (int mf = 0; mf < 4; ++mf) {
                    MMA16816(acc[mf][2*ng],   ah[mf][0], ah[mf][1], ah[mf][2], ah[mf][3],
                             bh[0], bh[1]);
                    MMA16816(acc[mf][2*ng+1], ah[mf][0], ah[mf][1], ah[mf][2], ah[mf][3],
                             bh[2], bh[3]);
                }
            }
        }
    }

    const int mrow = lane >> 2;
    const int ncol = (lane & 3) * 2;
    #pragma unroll
    for (int mf = 0; mf < 4; ++mf) {
        #pragma unroll
        for (int nf = 0; nf < 8; ++nf) {
            int m = m0 + wm * 64 + mf * 16 + mrow;
            int n = n0 + wn * 64 + nf * 8 + ncol;
            float b0 = bias[n], b1 = bias[n + 1];
            float v00 = (acc[mf][nf][0] + b0) * scale;
            float v01 = (acc[mf][nf][1] + b1) * scale;
            float v10 = (acc[mf][nf][2] + b0) * scale;
            float v11 = (acc[mf][nf][3] + b1) * scale;
            if (MODE == 0) {
                *(float2*)&C[(size_t)m * DD + n]       = make_float2(v00, v01);
                *(float2*)&C[(size_t)(m + 8) * DD + n] = make_float2(v10, v11);
            } else {
                int b = m >> 11, h = n >> 6, d = n & 63;
                int s  = m & (SS - 1);
                size_t o0 = (((size_t)(b * HH + h)) * SS + s) * DH + d;
                size_t o1 = o0 + 8 * DH;
                *(uint32_t*)(Ho + o0) = cvt2_f16(v00, v01);
                *(uint32_t*)(Ho + o1) = cvt2_f16(v10, v11);
            }
        }
    }
}

__global__ void __launch_bounds__(GT, 2)
qkv_mma_kernel(const float* __restrict__ bq, const float* __restrict__ bk,
               const float* __restrict__ bv) {
    int z = blockIdx.z;
    __half* Ho = (z == 0) ? g_q : (z == 1) ? g_k : g_v;
    const float* bias = (z == 0) ? bq : (z == 1) ? bk : bv;
    float scale = (z == 0) ? QSCALE : 1.0f;
    mma_gemm_body<1>(g_x16, g_wt + (size_t)z * DD * DD, bias, nullptr, Ho, scale);
}

__global__ void __launch_bounds__(GT, 2)
outproj_mma_kernel(const float* __restrict__ bo, float* __restrict__ out) {
    mma_gemm_body<0>(g_at16, g_wt + (size_t)3 * DD * DD, bo, out, nullptr, 1.0f);
}

// ---------------------------------------------------------------------------
// Tensor-core flash attention (fp16, causal, exp2 domain).
// CTA: 128 Q x 128 KV, 4 warps x 32 Q rows, 128 threads.
// R16: Q fragments register-resident (loaded once), l-reduction deferred to
// epilogue (per-thread partials). XOR-swizzled 128B rows, 3-buffer pipe.
// ---------------------------------------------------------------------------
#define AROWB 128
#define ATILE_BY (128 * AROWB)         // 16384
#define AQ_BY (128 * AROWB)            // 16384
#define ASTAGE_BY (2 * ATILE_BY)       // 32768
#define ANSTAGE 3
#define SMEM_ATT (AQ_BY + ANSTAGE * ASTAGE_BY)   // 114688
#define AT 128

__global__ void __launch_bounds__(AT, 2)
attn_mma_kernel()
{
    extern __shared__ char dynsmem[];
    const uint32_t base_u = smem_u32(dynsmem);
    const uint32_t sQ  = base_u;
    const uint32_t kvb = base_u + AQ_BY;

    const int tid  = threadIdx.x;
    const int w    = tid >> 5, lane = tid & 31;
    const int bh   = blockIdx.y;
    const int qt   = (int)(gridDim.x - 1 - blockIdx.x);   // heavy tiles first
    const int q0   = qt * 128;
    const int nt   = qt + 1;

    const size_t hb = (size_t)bh * SS * DH;
    const __half* qp = g_q + hb;
    const __half* kp = g_k + hb;
    const __half* vp = g_v + hb;

    auto load_q = [&]() {
        #pragma unroll
        for (int it = 0; it < 8; ++it) {
            int idx = tid + it * AT;
            int row = idx >> 3, seg = idx & 7;
            CP_ASYNC16(sQ + asw(row, seg), qp + (size_t)(q0 + row) * DH + seg * 8);
        }
    };
    auto issue_kv = [&](int kt, int st) {
        const int t0 = kt * 128;
        const __half* srcs[2] = { kp, vp };
        uint32_t sb = kvb + st * ASTAGE_BY;
        #pragma unroll
        for (int tile = 0; tile < 2; ++tile) {
            const __half* src = srcs[tile] + (size_t)t0 * DH;
            uint32_t dst = sb + tile * ATILE_BY;
            #pragma unroll
            for (int it = 0; it < 8; ++it) {
                int idx = tid + it * AT;
                int row = idx >> 3, seg = idx & 7;
                CP_ASYNC16(dst + asw(row, seg), src + (size_t)row * DH + seg * 8);
            }
        }
    };

    load_q(); issue_kv(0, 0); CP_COMMIT();
    if (nt > 1) issue_kv(1, 1);
    CP_COMMIT();

    float Oa[2][8][4];
    #pragma unroll
    for (int mf = 0; mf < 2; ++mf)
        #pragma unroll
        for (int i = 0; i < 8; ++i)
            #pragma unroll
            for (int j = 0; j < 4; ++j) Oa[mf][i][j] = 0.f;
    float m_run[2][2] = {{-1e30f, -1e30f}, {-1e30f, -1e30f}};
    float lp[2][2]    = {{0.f, 0.f}, {0.f, 0.f}};   // per-thread partial l

    const int qrow_l = (lane & 15);
    const int qchk_l = (lane >> 4) & 1;
    const int krow_l = (lane & 7) + ((lane >> 4) & 1) * 8;
    const int kchk_l = (lane >> 3) & 1;
    const int vrow_l = ((lane >> 3) & 1) * 8 + (lane & 7);
    const int vchk_l = (lane >> 4) & 1;

    uint32_t qf[2][4][4];   // register-resident Q fragments [mf][ks][4]

    for (int kt = 0; kt < nt; ++kt) {
        const int st = kt % ANSTAGE;
        const int t0 = kt * 128;
        CP_WAIT1();
        __syncthreads();
        if (kt + 2 < nt) issue_kv(kt + 2, (kt + 2) % ANSTAGE);
        CP_COMMIT();

        if (kt == 0) {
            #pragma unroll
            for (int mf = 0; mf < 2; ++mf)
                #pragma unroll
                for (int ks = 0; ks < 4; ++ks) {
                    int qr = 32 * w + 16 * mf + qrow_l;
                    LDSM_X4(qf[mf][ks][0], qf[mf][ks][1], qf[mf][ks][2], qf[mf][ks][3],
                            sQ + asw(qr, 2 * ks + qchk_l));
                }
        }

        const uint32_t sK = kvb + st * ASTAGE_BY;
        const uint32_t sV = sK + ATILE_BY;

        // ---- S = Q*K^T ----
        float acc[2][16][4];
        #pragma unroll
        for (int mf = 0; mf < 2; ++mf)
            #pragma unroll
            for (int i = 0; i < 16; ++i)
                #pragma unroll
                for (int j = 0; j < 4; ++j) acc[mf][i][j] = 0.f;

        #pragma unroll
        for (int ks = 0; ks < 4; ++ks) {
            #pragma unroll
            for (int ng = 0; ng < 8; ++ng) {
                int kr = 16 * ng + krow_l;
                uint32_t kH[4];
                LDSM_X4(kH[0], kH[1], kH[2], kH[3], sK + asw(kr, 2 * ks + kchk_l));
                #pragma unroll
                for (int mf = 0; mf < 2; ++mf) {
                    MMA16816(acc[mf][2*ng],   qf[mf][ks][0], qf[mf][ks][1],
                             qf[mf][ks][2], qf[mf][ks][3], kH[0], kH[1]);
                    MMA16816(acc[mf][2*ng+1], qf[mf][ks][0], qf[mf][ks][1],
                             qf[mf][ks][2], qf[mf][ks][3], kH[2], kH[3]);
                }
            }
        }

        // ---- causal mask (diagonal tile only) ----
        if (kt == qt) {
            int cb = t0 + 2 * (lane & 3);
            #pragma unroll
            for (int mf = 0; mf < 2; ++mf) {
                int rb = q0 + 32 * w + 16 * mf + (lane >> 2);
                #pragma unroll
                for (int nf = 0; nf < 16; ++nf) {
                    int c0 = cb + 8 * nf;
                    if (c0     > rb)     acc[mf][nf][0] = -1e30f;
                    if (c0 + 1 > rb)     acc[mf][nf][1] = -1e30f;
                    if (c0     > rb + 8) acc[mf][nf][2] = -1e30f;
                    if (c0 + 1 > rb + 8) acc[mf][nf][3] = -1e30f;
                }
            }
        }

        // ---- online softmax (exp2 domain); P packed in-place; deferred l ----
        #pragma unroll
        for (int mf = 0; mf < 2; ++mf) {
            float mx0 = -1e30f, mx1 = -1e30f;
            #pragma unroll
            for (int nf = 0; nf < 16; ++nf) {
                mx0 = fmaxf(mx0, fmaxf(acc[mf][nf][0], acc[mf][nf][1]));
                mx1 = fmaxf(mx1, fmaxf(acc[mf][nf][2], acc[mf][nf][3]));
            }
            mx0 = fmaxf(mx0, __shfl_xor_sync(0xffffffffu, mx0, 1));
            mx0 = fmaxf(mx0, __shfl_xor_sync(0xffffffffu, mx0, 2));
            mx1 = fmaxf(mx1, __shfl_xor_sync(0xffffffffu, mx1, 1));
            mx1 = fmaxf(mx1, __shfl_xor_sync(0xffffffffu, mx1, 2));

            float mn0 = fmaxf(m_run[mf][0], mx0), mn1 = fmaxf(m_run[mf][1], mx1);
            float corr0 = exp2f(m_run[mf][0] - mn0), corr1 = exp2f(m_run[mf][1] - mn1);

            float s0 = 0.f, s1 = 0.f;
            #pragma unroll
            for (int nf = 0; nf < 16; ++nf) {
                float p00 = exp2f(acc[mf][nf][0] - mn0);
                float p01 = exp2f(acc[mf][nf][1] - mn0);
                float p10 = exp2f(acc[mf][nf][2] - mn1);
                float p11 = exp2f(acc[mf][nf][3] - mn1);
                s0 += p00 + p01; s1 += p10 + p11;
                acc[mf][nf][0] = __uint_as_float(cvt2_f16(p00, p01));
                acc[mf][nf][1] = __uint_as_float(cvt2_f16(p10, p11));
            }
            // deferred l: per-thread partials only (corr uniform across quad)
            lp[mf][0] = lp[mf][0] * corr0 + s0;  m_run[mf][0] = mn0;
            lp[mf][1] = lp[mf][1] * corr1 + s1;  m_run[mf][1] = mn1;

            #pragma unroll
            for (int nf = 0; nf < 8; ++nf) {
                Oa[mf][nf][0] *= corr0; Oa[mf][nf][1] *= corr0;
                Oa[mf][nf][2] *= corr1; Oa[mf][nf][3] *= corr1;
            }
        }

        // ---- O += P*V ----
        #pragma unroll
        for (int kc = 0; kc < 8; ++kc) {
            #pragma unroll
            for (int p = 0; p < 4; ++p) {
                int vr = 16 * kc + vrow_l;
                uint32_t vH[4];
                LDSM_X4_T(vH[0], vH[1], vH[2], vH[3], sV + asw(vr, 2 * p + vchk_l));
                #pragma unroll
                for (int mf = 0; mf < 2; ++mf) {
                    uint32_t aH0 = __float_as_uint(acc[mf][2*kc][0]);
                    uint32_t aH1 = __float_as_uint(acc[mf][2*kc][1]);
                    uint32_t aH2 = __float_as_uint(acc[mf][2*kc+1][0]);
                    uint32_t aH3 = __float_as_uint(acc[mf][2*kc+1][1]);
                    MMA16816(Oa[mf][2*p],   aH0, aH1, aH2, aH3, vH[0], vH[1]);
                    MMA16816(Oa[mf][2*p+1], aH0, aH1, aH2, aH3, vH[2], vH[3]);
                }
            }
        }
    }

    // ---- final l reduction (once) + epilogue ----
    int b = bh >> 4, h = bh & (HH - 1);
    #pragma unroll
    for (int mf = 0; mf < 2; ++mf) {
        float l0 = lp[mf][0], l1 = lp[mf][1];
        l0 += __shfl_xor_sync(0xffffffffu, l0, 1);
        l0 += __shfl_xor_sync(0xffffffffu, l0, 2);
        l1 += __shfl_xor_sync(0xffffffffu, l1, 1);
        l1 += __shfl_xor_sync(0xffffffffu, l1, 2);
        float inv0 = 1.f / l0, inv1 = 1.f / l1;
        int r0 = q0 + 32 * w + 16 * mf + (lane >> 2);
        size_t ro0 = (size_t)(b * SS + r0) * DD + h * DH;
        size_t ro1 = ro0 + (size_t)8 * DD;
        #pragma unroll
        for (int nf = 0; nf < 8; ++nf) {
            int d = 8 * nf + 2 * (lane & 3);
            *(uint32_t*)(g_at16 + ro0 + d) =
                cvt2_f16(Oa[mf][nf][0] * inv0, Oa[mf][nf][1] * inv0);
            *(uint32_t*)(g_at16 + ro1 + d) =
                cvt2_f16(Oa[mf][nf][2] * inv1, Oa[mf][nf][3] * inv1);
        }
    }
}

// ---------------------------------------------------------------------------
extern "C" void kernel_launch(void* const* d_in, const int* in_sizes, int n_in,
                              void* d_out, int out_size)
{
    const float* x  = (const float*)d_in[0];
    const float* Wq = (const float*)d_in[1];
    const float* bq = (const float*)d_in[2];
    const float* Wk = (const float*)d_in[3];
    const float* bk = (const float*)d_in[4];
    const float* Wv = (const float*)d_in[5];
    const float* bv = (const float*)d_in[6];
    const float* Wo = (const float*)d_in[7];
    const float* bo = (const float*)d_in[8];
    float* out = (float*)d_out;

    cudaFuncSetAttribute(qkv_mma_kernel,
                         cudaFuncAttributeMaxDynamicSharedMemorySize, SMEM_MMA);
    cudaFuncSetAttribute(outproj_mma_kernel,
                         cudaFuncAttributeMaxDynamicSharedMemorySize, SMEM_MMA);
    cudaFuncSetAttribute(attn_mma_kernel,
                         cudaFuncAttributeMaxDynamicSharedMemorySize, SMEM_ATT);

    // 1) fused prep: x -> fp16 + transpose+convert all weights (one launch)
    {
        __half* xh;
        cudaGetSymbolAddress((void**)&xh, g_x16);
        prep_kernel<<<NSPLIT + 4096, 256>>>(x, Wq, Wk, Wv, Wo, xh);
    }

    // 2) QKV projections (fp16 HMMA, KC=64 single-barrier pipe)
    qkv_mma_kernel<<<dim3(DD / 128, MROWS / 128, 3), GT, SMEM_MMA>>>(bq, bk, bv);

    // 3) tensor-core causal flash attention (register-Q, deferred-l)
    attn_mma_kernel<<<dim3(SS / 128, BB * HH), AT, SMEM_ATT>>>();

    // 4) output projection
    outproj_mma_kernel<<<dim3(DD / 128, MROWS / 128), GT, SMEM_MMA>>>(bo, out);
}

// round 17
// speedup vs baseline: 1.0267x; 1.0267x over previous
#include <cuda_runtime.h>
#include <cuda_fp16.h>
#include <cstdint>
#include <math.h>
#include <string.h>

// Problem shape (fixed)
#define BB 4
#define SS 2048
#define DD 1024
#define HH 16
#define DH 64
#define MROWS (BB*SS)   // 8192

// ---------------------------------------------------------------------------
// Scratch (__device__ globals). Single-fp16 everywhere.
// q/k/v layout: [B*H][S][64]
// ---------------------------------------------------------------------------
__device__ __half g_q[(size_t)BB*HH*SS*DH];
__device__ __half g_k[(size_t)BB*HH*SS*DH];
__device__ __half g_v[(size_t)BB*HH*SS*DH];

__device__ __half g_x16[(size_t)MROWS*DD];
__device__ __half g_at16[(size_t)MROWS*DD];
// transposed weights: [4][N][K], Wt[n][k] = W[k][n]; 0..3 = q,k,v,o
__device__ __half g_wt[(size_t)4*DD*DD];

// ---------------------------------------------------------------------------
// Helpers (base-sm_103-safe)
// ---------------------------------------------------------------------------
__device__ __forceinline__ uint32_t smem_u32(const void* p) {
    uint32_t a;
    asm("{ .reg .u64 t; cvta.to.shared.u64 t, %1; cvt.u32.u64 %0, t; }"
        : "=r"(a) : "l"(p));
    return a;
}
#define CP_ASYNC16(dst_u32, src_ptr) \
    asm volatile("cp.async.cg.shared.global [%0], [%1], 16;" \
                 :: "r"(dst_u32), "l"(src_ptr))
#define CP_COMMIT() asm volatile("cp.async.commit_group;")
#define CP_WAIT1()  asm volatile("cp.async.wait_group 1;")

#define LDSM_X4(r0, r1, r2, r3, addr) \
    asm volatile("ldmatrix.sync.aligned.m8n8.x4.shared.b16 {%0,%1,%2,%3}, [%4];" \
                 : "=r"(r0), "=r"(r1), "=r"(r2), "=r"(r3) : "r"(addr))
#define LDSM_X4_T(r0, r1, r2, r3, addr) \
    asm volatile("ldmatrix.sync.aligned.m8n8.x4.trans.shared.b16 {%0,%1,%2,%3}, [%4];" \
                 : "=r"(r0), "=r"(r1), "=r"(r2), "=r"(r3) : "r"(addr))

#define MMA16816(d, a0, a1, a2, a3, b0, b1) \
    asm volatile("mma.sync.aligned.m16n8k16.row.col.f32.f16.f16.f32 " \
                 "{%0,%1,%2,%3}, {%4,%5,%6,%7}, {%8,%9}, {%0,%1,%2,%3};" \
                 : "+f"((d)[0]), "+f"((d)[1]), "+f"((d)[2]), "+f"((d)[3]) \
                 : "r"(a0), "r"(a1), "r"(a2), "r"(a3), "r"(b0), "r"(b1))

// packed f16x2 convert: result = {lo = cvt(a), hi = cvt(b)}  (RN rounding)
__device__ __forceinline__ uint32_t cvt2_f16(float a, float b) {
    uint32_t r;
    asm("cvt.rn.f16x2.f32 %0, %1, %2;" : "=r"(r) : "f"(b), "f"(a));
    return r;
}

// XOR swizzle for exact 128B rows: addr = row*128 + ((chunk ^ (row&7))*16)
__device__ __forceinline__ uint32_t asw(int row, int chunk) {
    return (uint32_t)(row * 128 + ((chunk ^ (row & 7)) << 4));
}

// q scale: (1/sqrt(64)) * log2(e), so softmax runs in exp2 domain
#define QSCALE 0.1803368801111204f

// ---------------------------------------------------------------------------
// Fused prep kernel (unchanged)
// ---------------------------------------------------------------------------
#define NSPLIT ((MROWS * DD) / (256 * 4))   // 8192

__global__ void __launch_bounds__(256)
prep_kernel(const float* __restrict__ x,
            const float* __restrict__ Wq, const float* __restrict__ Wk,
            const float* __restrict__ Wv, const float* __restrict__ Wo,
            __half* __restrict__ x16)
{
    int bid = blockIdx.x;
    if (bid < NSPLIT) {
        size_t i = ((size_t)bid * 256 + threadIdx.x) * 4;
        float4 v = *(const float4*)(x + i);
        *(uint32_t*)(x16 + i)     = cvt2_f16(v.x, v.y);
        *(uint32_t*)(x16 + i + 2) = cvt2_f16(v.z, v.w);
    } else {
        __shared__ float t[32][33];
        int tb = bid - NSPLIT;
        int z  = tb >> 10;
        int rem = tb & 1023;
        int k0 = (rem >> 5) * 32;
        int n0 = (rem & 31) * 32;
        const float* W = (z == 0) ? Wq : (z == 1) ? Wk : (z == 2) ? Wv : Wo;
        __half* Th = g_wt + (size_t)z * DD * DD;
        int tx = threadIdx.x & 31, ty = threadIdx.x >> 5;
        #pragma unroll
        for (int i = ty; i < 32; i += 8)
            t[i][tx] = W[(size_t)(k0 + i) * DD + n0 + tx];
        __syncthreads();
        #pragma unroll
        for (int i = ty; i < 32; i += 8) {
            size_t o = (size_t)(n0 + i) * DD + k0 + tx;
            Th[o] = __float2half(t[tx][i]);
        }
    }
}

// ---------------------------------------------------------------------------
// fp16 GEMM on mma.sync (unchanged from R15: KC=64, single-barrier 3-buffer).
// ---------------------------------------------------------------------------
#define KC 64
#define NCHUNK (DD / KC)              // 16
#define GTILE_BY (128 * 128)          // 16384
#define GSTAGE_BY (2 * GTILE_BY)      // 32768
#define GNSTAGE 3
#define SMEM_MMA (GNSTAGE * GSTAGE_BY)  // 98304
#define GT 128

template<int MODE>
__device__ __forceinline__ void mma_gemm_body(const __half* __restrict__ A,
                                              const __half* __restrict__ B,
                                              const float* __restrict__ bias,
                                              float* __restrict__ C,
                                              __half* __restrict__ Ho,
                                              float scale)
{
    extern __shared__ char dynsmem[];
    const uint32_t base_u = smem_u32(dynsmem);

    const int tid  = threadIdx.x;
    const int wid  = tid >> 5, lane = tid & 31;
    const int wm   = wid & 1;
    const int wn   = wid >> 1;
    const int m0   = blockIdx.y * 128;
    const int n0   = blockIdx.x * 128;

    const __half* srcs[2] = { A, B };
    const int rowbase[2] = { m0, n0 };

    auto issue_stage = [&](int c, int st) {
        #pragma unroll
        for (int tile = 0; tile < 2; ++tile) {
            const __half* src = srcs[tile] + (size_t)rowbase[tile] * DD + c * KC;
            uint32_t dst = base_u + st * GSTAGE_BY + tile * GTILE_BY;
            #pragma unroll
            for (int it = 0; it < 8; ++it) {
                int idx = tid + it * GT;
                int row = idx >> 3;
                int seg = idx & 7;
                CP_ASYNC16(dst + asw(row, seg), src + (size_t)row * DD + seg * 8);
            }
        }
    };

    float acc[4][8][4];
    #pragma unroll
    for (int i = 0; i < 4; ++i)
        #pragma unroll
        for (int j = 0; j < 8; ++j)
            #pragma unroll
            for (int q = 0; q < 4; ++q) acc[i][j][q] = 0.f;

    const int arow_l = (lane & 15);
    const int achk_l = (lane >> 4) & 1;
    const int brow_l = (lane & 7) + ((lane >> 4) & 1) * 8;
    const int bchk_l = (lane >> 3) & 1;

    issue_stage(0, 0); CP_COMMIT();
    issue_stage(1, 1); CP_COMMIT();

    for (int c = 0; c < NCHUNK; ++c) {
        const int st = c % GNSTAGE;
        CP_WAIT1();
        __syncthreads();
        if (c + 2 < NCHUNK) issue_stage(c + 2, (c + 2) % GNSTAGE);
        CP_COMMIT();

        const uint32_t sA = base_u + st * GSTAGE_BY;
        const uint32_t sB = sA + GTILE_BY;

        #pragma unroll
        for (int ks = 0; ks < 4; ++ks) {
            uint32_t ah[4][4];
            #pragma unroll
            for (int mf = 0; mf < 4; ++mf) {
                int ar = wm * 64 + mf * 16 + arow_l;
                LDSM_X4(ah[mf][0], ah[mf][1], ah[mf][2], ah[mf][3],
                        sA + asw(ar, 2 * ks + achk_l));
            }
            #pragma unroll
            for (int ng = 0; ng < 4; ++ng) {
                uint32_t bh[4];
                int br = wn * 64 + ng * 16 + brow_l;
                LDSM_X4(bh[0], bh[1], bh[2], bh[3], sB + asw(br, 2 * ks + bchk_l));
                #pragma unroll
                for (int mf = 0; mf < 4; ++mf) {
                    MMA16816(acc[mf][2*ng],   ah[mf][0], ah[mf][1], ah[mf][2], ah[mf][3],
                             bh[0], bh[1]);
                    MMA16816(acc[mf][2*ng+1], ah[mf][0], ah[mf][1], ah[mf][2], ah[mf][3],
                             bh[2], bh[3]);
                }
            }
        }
    }

    const int mrow = lane >> 2;
    const int ncol = (lane & 3) * 2;
    #pragma unroll
    for (int mf = 0; mf < 4; ++mf) {
        #pragma unroll
        for (int nf = 0; nf < 8; ++nf) {
            int m = m0 + wm * 64 + mf * 16 + mrow;
            int n = n0 + wn * 64 + nf * 8 + ncol;
            float b0 = bias[n], b1 = bias[n + 1];
            float v00 = (acc[mf][nf][0] + b0) * scale;
            float v01 = (acc[mf][nf][1] + b1) * scale;
            float v10 = (acc[mf][nf][2] + b0) * scale;
            float v11 = (acc[mf][nf][3] + b1) * scale;
            if (MODE == 0) {
                *(float2*)&C[(size_t)m * DD + n]       = make_float2(v00, v01);
                *(float2*)&C[(size_t)(m + 8) * DD + n] = make_float2(v10, v11);
            } else {
                int b = m >> 11, h = n >> 6, d = n & 63;
                int s  = m & (SS - 1);
                size_t o0 = (((size_t)(b * HH + h)) * SS + s) * DH + d;
                size_t o1 = o0 + 8 * DH;
                *(uint32_t*)(Ho + o0) = cvt2_f16(v00, v01);
                *(uint32_t*)(Ho + o1) = cvt2_f16(v10, v11);
            }
        }
    }
}

__global__ void __launch_bounds__(GT, 2)
qkv_mma_kernel(const float* __restrict__ bq, const float* __restrict__ bk,
               const float* __restrict__ bv) {
    int z = blockIdx.z;
    __half* Ho = (z == 0) ? g_q : (z == 1) ? g_k : g_v;
    const float* bias = (z == 0) ? bq : (z == 1) ? bk : bv;
    float scale = (z == 0) ? QSCALE : 1.0f;
    mma_gemm_body<1>(g_x16, g_wt + (size_t)z * DD * DD, bias, nullptr, Ho, scale);
}

__global__ void __launch_bounds__(GT, 2)
outproj_mma_kernel(const float* __restrict__ bo, float* __restrict__ out) {
    mma_gemm_body<0>(g_at16, g_wt + (size_t)3 * DD * DD, bo, out, nullptr, 1.0f);
}

// ---------------------------------------------------------------------------
// Tensor-core flash attention (fp16, causal, exp2 domain).
// CTA: 128 Q x 128 KV, 4 warps x 32 Q rows, 128 threads.
// R15 structure (per-tile Q LDSM) + deferred-l only (zero extra registers).
// XOR-swizzled 128B rows, 3-buffer single-barrier pipeline.
// ---------------------------------------------------------------------------
#define AROWB 128
#define ATILE_BY (128 * AROWB)         // 16384
#define AQ_BY (128 * AROWB)            // 16384
#define ASTAGE_BY (2 * ATILE_BY)       // 32768
#define ANSTAGE 3
#define SMEM_ATT (AQ_BY + ANSTAGE * ASTAGE_BY)   // 114688
#define AT 128

__global__ void __launch_bounds__(AT, 2)
attn_mma_kernel()
{
    extern __shared__ char dynsmem[];
    const uint32_t base_u = smem_u32(dynsmem);
    const uint32_t sQ  = base_u;
    const uint32_t kvb = base_u + AQ_BY;

    const int tid  = threadIdx.x;
    const int w    = tid >> 5, lane = tid & 31;
    const int bh   = blockIdx.y;
    const int qt   = (int)(gridDim.x - 1 - blockIdx.x);   // heavy tiles first
    const int q0   = qt * 128;
    const int nt   = qt + 1;

    const size_t hb = (size_t)bh * SS * DH;
    const __half* qp = g_q + hb;
    const __half* kp = g_k + hb;
    const __half* vp = g_v + hb;

    auto load_q = [&]() {
        #pragma unroll
        for (int it = 0; it < 8; ++it) {
            int idx = tid + it * AT;
            int row = idx >> 3, seg = idx & 7;
            CP_ASYNC16(sQ + asw(row, seg), qp + (size_t)(q0 + row) * DH + seg * 8);
        }
    };
    auto issue_kv = [&](int kt, int st) {
        const int t0 = kt * 128;
        const __half* srcs[2] = { kp, vp };
        uint32_t sb = kvb + st * ASTAGE_BY;
        #pragma unroll
        for (int tile = 0; tile < 2; ++tile) {
            const __half* src = srcs[tile] + (size_t)t0 * DH;
            uint32_t dst = sb + tile * ATILE_BY;
            #pragma unroll
            for (int it = 0; it < 8; ++it) {
                int idx = tid + it * AT;
                int row = idx >> 3, seg = idx & 7;
                CP_ASYNC16(dst + asw(row, seg), src + (size_t)row * DH + seg * 8);
            }
        }
    };

    load_q(); issue_kv(0, 0); CP_COMMIT();
    if (nt > 1) issue_kv(1, 1);
    CP_COMMIT();

    float Oa[2][8][4];
    #pragma unroll
    for (int mf = 0; mf < 2; ++mf)
        #pragma unroll
        for (int i = 0; i < 8; ++i)
            #pragma unroll
            for (int j = 0; j < 4; ++j) Oa[mf][i][j] = 0.f;
    float m_run[2][2] = {{-1e30f, -1e30f}, {-1e30f, -1e30f}};
    float lp[2][2]    = {{0.f, 0.f}, {0.f, 0.f}};   // per-thread partial l

    const int qrow_l = (lane & 15);
    const int qchk_l = (lane >> 4) & 1;
    const int krow_l = (lane & 7) + ((lane >> 4) & 1) * 8;
    const int kchk_l = (lane >> 3) & 1;
    const int vrow_l = ((lane >> 3) & 1) * 8 + (lane & 7);
    const int vchk_l = (lane >> 4) & 1;

    for (int kt = 0; kt < nt; ++kt) {
        const int st = kt % ANSTAGE;
        const int t0 = kt * 128;
        CP_WAIT1();
        __syncthreads();
        if (kt + 2 < nt) issue_kv(kt + 2, (kt + 2) % ANSTAGE);
        CP_COMMIT();

        const uint32_t sK = kvb + st * ASTAGE_BY;
        const uint32_t sV = sK + ATILE_BY;

        // ---- S = Q*K^T ----
        float acc[2][16][4];
        #pragma unroll
        for (int mf = 0; mf < 2; ++mf)
            #pragma unroll
            for (int i = 0; i < 16; ++i)
                #pragma unroll
                for (int j = 0; j < 4; ++j) acc[mf][i][j] = 0.f;

        #pragma unroll
        for (int ks = 0; ks < 4; ++ks) {
            uint32_t aH[2][4];
            #pragma unroll
            for (int mf = 0; mf < 2; ++mf) {
                int qr = 32 * w + 16 * mf + qrow_l;
                LDSM_X4(aH[mf][0], aH[mf][1], aH[mf][2], aH[mf][3],
                        sQ + asw(qr, 2 * ks + qchk_l));
            }
            #pragma unroll
            for (int ng = 0; ng < 8; ++ng) {
                int kr = 16 * ng + krow_l;
                uint32_t kH[4];
                LDSM_X4(kH[0], kH[1], kH[2], kH[3], sK + asw(kr, 2 * ks + kchk_l));
                #pragma unroll
                for (int mf = 0; mf < 2; ++mf) {
                    MMA16816(acc[mf][2*ng],   aH[mf][0], aH[mf][1], aH[mf][2], aH[mf][3],
                             kH[0], kH[1]);
                    MMA16816(acc[mf][2*ng+1], aH[mf][0], aH[mf][1], aH[mf][2], aH[mf][3],
                             kH[2], kH[3]);
                }
            }
        }

        // ---- causal mask (diagonal tile only) ----
        if (kt == qt) {
            int cb = t0 + 2 * (lane & 3);
            #pragma unroll
            for (int mf = 0; mf < 2; ++mf) {
                int rb = q0 + 32 * w + 16 * mf + (lane >> 2);
                #pragma unroll
                for (int nf = 0; nf < 16; ++nf) {
                    int c0 = cb + 8 * nf;
                    if (c0     > rb)     acc[mf][nf][0] = -1e30f;
                    if (c0 + 1 > rb)     acc[mf][nf][1] = -1e30f;
                    if (c0     > rb + 8) acc[mf][nf][2] = -1e30f;
                    if (c0 + 1 > rb + 8) acc[mf][nf][3] = -1e30f;
                }
            }
        }

        // ---- online softmax (exp2 domain); P packed in-place; deferred l ----
        #pragma unroll
        for (int mf = 0; mf < 2; ++mf) {
            float mx0 = -1e30f, mx1 = -1e30f;
            #pragma unroll
            for (int nf = 0; nf < 16; ++nf) {
                mx0 = fmaxf(mx0, fmaxf(acc[mf][nf][0], acc[mf][nf][1]));
                mx1 = fmaxf(mx1, fmaxf(acc[mf][nf][2], acc[mf][nf][3]));
            }
            mx0 = fmaxf(mx0, __shfl_xor_sync(0xffffffffu, mx0, 1));
            mx0 = fmaxf(mx0, __shfl_xor_sync(0xffffffffu, mx0, 2));
            mx1 = fmaxf(mx1, __shfl_xor_sync(0xffffffffu, mx1, 1));
            mx1 = fmaxf(mx1, __shfl_xor_sync(0xffffffffu, mx1, 2));

            float mn0 = fmaxf(m_run[mf][0], mx0), mn1 = fmaxf(m_run[mf][1], mx1);
            float corr0 = exp2f(m_run[mf][0] - mn0), corr1 = exp2f(m_run[mf][1] - mn1);

            float s0 = 0.f, s1 = 0.f;
            #pragma unroll
            for (int nf = 0; nf < 16; ++nf) {
                float p00 = exp2f(acc[mf][nf][0] - mn0);
                float p01 = exp2f(acc[mf][nf][1] - mn0);
                float p10 = exp2f(acc[mf][nf][2] - mn1);
                float p11 = exp2f(acc[mf][nf][3] - mn1);
                s0 += p00 + p01; s1 += p10 + p11;
                acc[mf][nf][0] = __uint_as_float(cvt2_f16(p00, p01));
                acc[mf][nf][1] = __uint_as_float(cvt2_f16(p10, p11));
            }
            // deferred l: per-thread partials only (corr uniform across quad)
            lp[mf][0] = lp[mf][0] * corr0 + s0;  m_run[mf][0] = mn0;
            lp[mf][1] = lp[mf][1] * corr1 + s1;  m_run[mf][1] = mn1;

            #pragma unroll
            for (int nf = 0; nf < 8; ++nf) {
                Oa[mf][nf][0] *= corr0; Oa[mf][nf][1] *= corr0;
                Oa[mf][nf][2] *= corr1; Oa[mf][nf][3] *= corr1;
            }
        }

        // ---- O += P*V ----
        #pragma unroll
        for (int kc = 0; kc < 8; ++kc) {
            #pragma unroll
            for (int p = 0; p < 4; ++p) {
                int vr = 16 * kc + vrow_l;
                uint32_t vH[4];
                LDSM_X4_T(vH[0], vH[1], vH[2], vH[3], sV + asw(vr, 2 * p + vchk_l));
                #pragma unroll
                for (int mf = 0; mf < 2; ++mf) {
                    uint32_t aH0 = __float_as_uint(acc[mf][2*kc][0]);
                    uint32_t aH1 = __float_as_uint(acc[mf][2*kc][1]);
                    uint32_t aH2 = __float_as_uint(acc[mf][2*kc+1][0]);
                    uint32_t aH3 = __float_as_uint(acc[mf][2*kc+1][1]);
                    MMA16816(Oa[mf][2*p],   aH0, aH1, aH2, aH3, vH[0], vH[1]);
                    MMA16816(Oa[mf][2*p+1], aH0, aH1, aH2, aH3, vH[2], vH[3]);
                }
            }
        }
    }

    // ---- final l reduction (once) + epilogue ----
    int b = bh >> 4, h = bh & (HH - 1);
    #pragma unroll
    for (int mf = 0; mf < 2; ++mf) {
        float l0 = lp[mf][0], l1 = lp[mf][1];
        l0 += __shfl_xor_sync(0xffffffffu, l0, 1);
        l0 += __shfl_xor_sync(0xffffffffu, l0, 2);
        l1 += __shfl_xor_sync(0xffffffffu, l1, 1);
        l1 += __shfl_xor_sync(0xffffffffu, l1, 2);
        float inv0 = 1.f / l0, inv1 = 1.f / l1;
        int r0 = q0 + 32 * w + 16 * mf + (lane >> 2);
        size_t ro0 = (size_t)(b * SS + r0) * DD + h * DH;
        size_t ro1 = ro0 + (size_t)8 * DD;
        #pragma unroll
        for (int nf = 0; nf < 8; ++nf) {
            int d = 8 * nf + 2 * (lane & 3);
            *(uint32_t*)(g_at16 + ro0 + d) =
                cvt2_f16(Oa[mf][nf][0] * inv0, Oa[mf][nf][1] * inv0);
            *(uint32_t*)(g_at16 + ro1 + d) =
                cvt2_f16(Oa[mf][nf][2] * inv1, Oa[mf][nf][3] * inv1);
        }
    }
}

// ---------------------------------------------------------------------------
extern "C" void kernel_launch(void* const* d_in, const int* in_sizes, int n_in,
                              void* d_out, int out_size)
{
    const float* x  = (const float*)d_in[0];
    const float* Wq = (const float*)d_in[1];
    const float* bq = (const float*)d_in[2];
    const float* Wk = (const float*)d_in[3];
    const float* bk = (const float*)d_in[4];
    const float* Wv = (const float*)d_in[5];
    const float* bv = (const float*)d_in[6];
    const float* Wo = (const float*)d_in[7];
    const float* bo = (const float*)d_in[8];
    float* out = (float*)d_out;

    cudaFuncSetAttribute(qkv_mma_kernel,
                         cudaFuncAttributeMaxDynamicSharedMemorySize, SMEM_MMA);
    cudaFuncSetAttribute(outproj_mma_kernel,
                         cudaFuncAttributeMaxDynamicSharedMemorySize, SMEM_MMA);
    cudaFuncSetAttribute(attn_mma_kernel,
                         cudaFuncAttributeMaxDynamicSharedMemorySize, SMEM_ATT);

    // 1) fused prep: x -> fp16 + transpose+convert all weights (one launch)
    {
        __half* xh;
        cudaGetSymbolAddress((void**)&xh, g_x16);
        prep_kernel<<<NSPLIT + 4096, 256>>>(x, Wq, Wk, Wv, Wo, xh);
    }

    // 2) QKV projections (fp16 HMMA, KC=64 single-barrier pipe)
    qkv_mma_kernel<<<dim3(DD / 128, MROWS / 128, 3), GT, SMEM_MMA>>>(bq, bk, bv);

    // 3) tensor-core causal flash attention (per-tile Q LDSM, deferred-l)
    attn_mma_kernel<<<dim3(SS / 128, BB * HH), AT, SMEM_ATT>>>();

    // 4) output projection
    outproj_mma_kernel<<<dim3(DD / 128, MROWS / 128), GT, SMEM_MMA>>>(bo, out);
}